// round 5
// baseline (speedup 1.0000x reference)
#include <cuda_runtime.h>
#include <cstdint>

// Problem dims (fixed)
#define ZD 16
#define YD 384
#define XD 384
#define YP 386        // padded y rows in E/ZC (row 0 and 385 stay zero)
#define NWIN_I 17     // z-pairs
#define NWIN_Y 385    // window rows
#define NGX 12        // 32-window groups per row; group 11 also does window x=384
#define TOTAL_B_THREADS (NWIN_I * NWIN_Y * NGX)          // 78540
#define B_BLOCKS ((TOTAL_B_THREADS + 255) / 256)          // 307
#define NP_WIN 148225.0                                   // 385*385
#define SLAB (YD * XD)                                    // 147456

// Scratch (static __device__ — zero-initialized; padded rows never written)
__device__ float         g_E[NWIN_I * YP * XD];   // z-pair sums of (s-l)^2
__device__ unsigned char g_ZC[NWIN_I * YP * XD];  // z-pair code: l0@0,l1@2,p0@4,p1@6
__device__ float         g_part[3 * B_BLOCKS];
__device__ unsigned      g_count;

// ---------------------------------------------------------------------------
// k1: z-pass. One thread per (y,x) column; walks z, emits 17 z-pair sums+codes.
__global__ void k1(const float* __restrict__ pred, const int* __restrict__ lab) {
    int x = threadIdx.x;
    int y = blockIdx.x;
    if (x == 0 && y == 0) g_count = 0u;
    int base = y * XD + x;
    int obase = (y + 1) * XD + x;   // padded row index

    float dprev = 0.f;
    unsigned cprev = 0u;
#pragma unroll 4
    for (int z = 0; z < ZD; z++) {
        float p = __ldg(&pred[z * SLAB + base]);
        int   l = __ldg(&lab[z * SLAB + base]);
        float s = __fdividef(1.f, 1.f + __expf(-p));
        float f = (float)l;
        float d = (s - f) * (s - f);
        unsigned c = (unsigned)(l & 1) | (p > 0.f ? 0x10u : 0u);  // lab@0, pred@4
        g_E[z * (YP * XD) + obase]  = dprev + d;
        g_ZC[z * (YP * XD) + obase] = (unsigned char)(cprev | (c << 2));
        dprev = d;
        cprev = c;
    }
    g_E[ZD * (YP * XD) + obase]  = dprev;
    g_ZC[ZD * (YP * XD) + obase] = (unsigned char)cprev;
}

// ---------------------------------------------------------------------------
// Rare-path BCE: byte==0 -> softplus(p), byte==255 -> softplus(-p).
__device__ __noinline__ float bce8(const float* __restrict__ pred, int i, int yw, int x, bool ones) {
    float s = 0.f;
#pragma unroll
    for (int dz = 0; dz < 2; dz++)
#pragma unroll
        for (int dy = 0; dy < 2; dy++)
#pragma unroll
            for (int dx = 0; dx < 2; dx++) {
                int z = i - 1 + dz, y = yw - 1 + dy, xv = x - 1 + dx;
                if (z >= 0 && z < ZD && y >= 0 && y < YD && xv >= 0 && xv < XD) {
                    float p = __ldg(&pred[(z * YD + y) * XD + xv]);
                    float u = ones ? -p : p;
                    s += fmaxf(u, 0.f) + __logf(1.f + __expf(-fabsf(u)));
                }
            }
    return s;
}

__device__ __forceinline__ unsigned wsel(uint4 u, int j) {
    return j == 0 ? u.x : (j == 1 ? u.y : (j == 2 ? u.z : u.w));
}

__device__ __forceinline__ float warp_sum(float v) {
#pragma unroll
    for (int off = 16; off > 0; off >>= 1)
        v += __shfl_down_sync(0xffffffffu, v, off);
    return v;
}

// ---------------------------------------------------------------------------
// k2: each thread sweeps 32 consecutive windows along x for a fixed (i, yw).
// Group 11 additionally handles the x=384 edge window (zero right column).
// Single wave: 307 blocks at 3+ CTAs/SM. Last block does the final reduce.
__global__ void __launch_bounds__(256, 3)
k2(const float* __restrict__ pred, const float* __restrict__ area,
   float* __restrict__ out) {
    __shared__ float a_sh[256];
    __shared__ float wN[8], wD[8], wB[8];
    __shared__ bool is_last;
    int tid = threadIdx.x;

    // permuted area LUT: index = (leftcol_nibble<<4)|rightcol_nibble,
    // nibble bit m = dz*2+dy -> true byte bit 2m+dx (left dx=0, right dx=1)
    {
        int a = tid >> 4, b = tid & 15;
        int byte = 0;
#pragma unroll
        for (int m = 0; m < 4; m++) {
            byte |= ((a >> m) & 1) << (2 * m);
            byte |= ((b >> m) & 1) << (2 * m + 1);
        }
        a_sh[tid] = __ldg(&area[byte]);
    }
    __syncthreads();

    float accN = 0.f, accLa = 0.f, accPa = 0.f, accB = 0.f;
    int t = blockIdx.x * 256 + tid;
    if (t < TOTAL_B_THREADS) {
        int g = t % NGX;
        int rem = t / NGX;
        int yw = rem % NWIN_Y;
        int i = rem / NWIN_Y;
        int x0 = g * 32;

        int rA = (i * YP + yw) * XD;
        int rB = rA + XD;

        float Fp;
        unsigned cbp;
        if (x0 == 0) {
            Fp = 0.f;
            cbp = 0u;
        } else {
            int c = x0 - 1;
            Fp = g_E[rA + c] + g_E[rB + c];
            cbp = (unsigned)g_ZC[rA + c] | ((unsigned)g_ZC[rB + c] << 1);
        }

#pragma unroll
        for (int half = 0; half < 2; half++) {
            int hb = x0 + half * 16;
            const float4* pA = reinterpret_cast<const float4*>(g_E + rA + hb);
            const float4* pB = reinterpret_cast<const float4*>(g_E + rB + hb);
            float4 eA0 = pA[0], eA1 = pA[1], eA2 = pA[2], eA3 = pA[3];
            float4 eB0 = pB[0], eB1 = pB[1], eB2 = pB[2], eB3 = pB[3];
            uint4 zA = *reinterpret_cast<const uint4*>(g_ZC + rA + hb);
            uint4 zB = *reinterpret_cast<const uint4*>(g_ZC + rB + hb);

#pragma unroll
            for (int j = 0; j < 4; j++) {
                float4 ea = j == 0 ? eA0 : (j == 1 ? eA1 : (j == 2 ? eA2 : eA3));
                float4 eb = j == 0 ? eB0 : (j == 1 ? eB1 : (j == 2 ? eB2 : eB3));
                // column codes: zc bytes <= 0x55, so <<1 can't cross byte lanes
                unsigned cw = wsel(zA, j) | (wsel(zB, j) << 1);
                float F0 = ea.x + eb.x;
                float F1 = ea.y + eb.y;
                float F2 = ea.z + eb.z;
                float F3 = ea.w + eb.w;
                float Fv[4] = {F0, F1, F2, F3};

#pragma unroll
                for (int k = 0; k < 4; k++) {
                    unsigned cb = __byte_perm(cw, 0u, 0x4440u | (unsigned)k);
                    float Fc = Fv[k];
                    float q = Fp + Fc;
                    unsigned lidx = ((cbp << 4) & 0xF0u) | (cb & 0x0Fu);
                    unsigned pidx = (cbp & 0xF0u) | (cb >> 4);
                    float la = a_sh[lidx];
                    float pa = a_sh[pidx];
                    float pw = fmaf(q, -0.125f, 1.0f);
                    accN = fmaf(pw, la, accN);
                    accLa += la;
                    accPa += pa;
                    if (((lidx + 1u) & 0xFFu) < 2u) {   // lidx==0 || lidx==255
                        accB += bce8(pred, i, yw, hb + 4 * j + k, lidx == 255u);
                    }
                    Fp = Fc;
                    cbp = cb;
                }
            }
        }

        // group 11: edge window x=384 (right column is zero padding)
        if (g == NGX - 1) {
            float q = Fp;
            unsigned lidx = (cbp << 4) & 0xF0u;
            unsigned pidx = cbp & 0xF0u;
            float la = a_sh[lidx];
            float pa = a_sh[pidx];
            float pw = fmaf(q, -0.125f, 1.0f);
            accN = fmaf(pw, la, accN);
            accLa += la;
            accPa += pa;
            if (((lidx + 1u) & 0xFFu) < 2u) {
                accB += bce8(pred, i, yw, 384, lidx == 255u);
            }
        }
    }
    float accD = accLa + accPa;

    // deterministic warp-shuffle reduction
    accN = warp_sum(accN);
    accD = warp_sum(accD);
    accB = warp_sum(accB);
    int lane = tid & 31, warp = tid >> 5;
    if (lane == 0) { wN[warp] = accN; wD[warp] = accD; wB[warp] = accB; }
    __syncthreads();
    if (warp == 0) {
        float vN = lane < 8 ? wN[lane] : 0.f;
        float vD = lane < 8 ? wD[lane] : 0.f;
        float vB = lane < 8 ? wB[lane] : 0.f;
#pragma unroll
        for (int off = 4; off > 0; off >>= 1) {
            vN += __shfl_down_sync(0xffffffffu, vN, off);
            vD += __shfl_down_sync(0xffffffffu, vD, off);
            vB += __shfl_down_sync(0xffffffffu, vB, off);
        }
        if (lane == 0) {
            g_part[3 * blockIdx.x + 0] = vN;
            g_part[3 * blockIdx.x + 1] = vD;
            g_part[3 * blockIdx.x + 2] = vB;
        }
    }

    __threadfence();
    if (tid == 0) {
        unsigned prev = atomicAdd(&g_count, 1u);
        is_last = (prev == B_BLOCKS - 1);
    }
    __syncthreads();
    if (!is_last) return;

    double sN = 0.0, sD = 0.0, sB = 0.0;
    for (int b = tid; b < B_BLOCKS; b += 256) {
        sN += (double)g_part[3 * b + 0];
        sD += (double)g_part[3 * b + 1];
        sB += (double)g_part[3 * b + 2];
    }
    __shared__ double rd[256];
    rd[tid] = sN; __syncthreads();
    for (int s = 128; s > 0; s >>= 1) { if (tid < s) rd[tid] += rd[tid + s]; __syncthreads(); }
    double tN = rd[0]; __syncthreads();
    rd[tid] = sD; __syncthreads();
    for (int s = 128; s > 0; s >>= 1) { if (tid < s) rd[tid] += rd[tid + s]; __syncthreads(); }
    double tD = rd[0]; __syncthreads();
    rd[tid] = sB; __syncthreads();
    for (int s = 128; s > 0; s >>= 1) { if (tid < s) rd[tid] += rd[tid + s]; __syncthreads(); }
    double tB = rd[0];

    if (tid == 0) {
        double dice = 1.0 - (2.0 * tN + 1e-3) / (tD + 1e-3);
        double vol = tB / (8.0 * NP_WIN);
        out[0] = (float)(dice + vol);
    }
}

// ---------------------------------------------------------------------------
extern "C" void kernel_launch(void* const* d_in, const int* in_sizes, int n_in,
                              void* d_out, int out_size) {
    const float* pred   = (const float*)d_in[0];
    const int*   labels = (const int*)d_in[1];
    const float* area   = (const float*)d_in[2];

    k1<<<YD, XD>>>(pred, labels);
    k2<<<B_BLOCKS, 256>>>(pred, area, (float*)d_out);
}

// round 9
// speedup vs baseline: 1.1718x; 1.1718x over previous
#include <cuda_runtime.h>
#include <cstdint>

// Problem dims (fixed)
#define ZD 16
#define YD 384
#define XD 384
#define YP 386        // padded y rows in E/ZC (row 0 and 385 stay zero)
#define NWIN_I 17     // z-pairs
#define NWIN_Y 385    // window rows
#define NGX 24        // 16-window groups; group 23 also does edge window x=384
#define TOTAL_B_THREADS (NWIN_I * NWIN_Y * NGX)          // 157080
#define B_BLOCKS ((TOTAL_B_THREADS + 255) / 256)          // 614
#define NP_WIN 148225.0                                   // 385*385
#define SLAB (YD * XD)                                    // 147456

// Scratch (static __device__ — zero-initialized; padded rows never written)
__device__ float         g_E[NWIN_I * YP * XD];   // z-pair sums of (s-l)^2
__device__ unsigned char g_ZC[NWIN_I * YP * XD];  // z-pair code: l0@0,l1@2,p0@4,p1@6
__device__ float         g_part[3 * B_BLOCKS];
__device__ unsigned      g_count;

// ---------------------------------------------------------------------------
// k1: z-pass. One thread per (y,x) column; walks z, emits 17 z-pair sums+codes.
__global__ void k1(const float* __restrict__ pred, const int* __restrict__ lab) {
    int x = threadIdx.x;
    int y = blockIdx.x;
    if (x == 0 && y == 0) g_count = 0u;
    int base = y * XD + x;
    int obase = (y + 1) * XD + x;   // padded row index

    float dprev = 0.f;
    unsigned cprev = 0u;
#pragma unroll 4
    for (int z = 0; z < ZD; z++) {
        float p = __ldg(&pred[z * SLAB + base]);
        int   l = __ldg(&lab[z * SLAB + base]);
        float s = __fdividef(1.f, 1.f + __expf(-p));
        float f = (float)l;
        float d = (s - f) * (s - f);
        unsigned c = (unsigned)(l & 1) | (p > 0.f ? 0x10u : 0u);  // lab@0, pred@4
        g_E[z * (YP * XD) + obase]  = dprev + d;
        g_ZC[z * (YP * XD) + obase] = (unsigned char)(cprev | (c << 2));
        dprev = d;
        cprev = c;
    }
    g_E[ZD * (YP * XD) + obase]  = dprev;
    g_ZC[ZD * (YP * XD) + obase] = (unsigned char)cprev;
}

// ---------------------------------------------------------------------------
// Rare-path BCE: byte==0 -> softplus(p), byte==255 -> softplus(-p).
__device__ __noinline__ float bce8(const float* __restrict__ pred, int i, int yw, int x, bool ones) {
    float s = 0.f;
#pragma unroll
    for (int dz = 0; dz < 2; dz++)
#pragma unroll
        for (int dy = 0; dy < 2; dy++)
#pragma unroll
            for (int dx = 0; dx < 2; dx++) {
                int z = i - 1 + dz, y = yw - 1 + dy, xv = x - 1 + dx;
                if (z >= 0 && z < ZD && y >= 0 && y < YD && xv >= 0 && xv < XD) {
                    float p = __ldg(&pred[(z * YD + y) * XD + xv]);
                    float u = ones ? -p : p;
                    s += fmaxf(u, 0.f) + __logf(1.f + __expf(-fabsf(u)));
                }
            }
    return s;
}

__device__ __forceinline__ float warp_sum(float v) {
#pragma unroll
    for (int off = 16; off > 0; off >>= 1)
        v += __shfl_down_sync(0xffffffffu, v, off);
    return v;
}

// ---------------------------------------------------------------------------
// k2: each thread sweeps 16 consecutive windows along x for a fixed (i, yw).
// Group 23 also handles the x=384 edge window (zero right column).
// 614 blocks @ 6 CTAs/SM -> all CTAs resident in a single wave.
__global__ void __launch_bounds__(256, 6)
k2(const float* __restrict__ pred, const float* __restrict__ area,
   float* __restrict__ out) {
    __shared__ float a_sh[256];
    __shared__ float wN[8], wD[8], wB[8];
    __shared__ bool is_last;
    int tid = threadIdx.x;

    // permuted area LUT: index = (leftcol_nibble<<4)|rightcol_nibble,
    // nibble bit m = dz*2+dy -> true byte bit 2m+dx (left dx=0, right dx=1)
    {
        int a = tid >> 4, b = tid & 15;
        int byte = 0;
#pragma unroll
        for (int m = 0; m < 4; m++) {
            byte |= ((a >> m) & 1) << (2 * m);
            byte |= ((b >> m) & 1) << (2 * m + 1);
        }
        a_sh[tid] = __ldg(&area[byte]);
    }
    __syncthreads();

    float S1 = 0.f, S2 = 0.f, Sq = 0.f, accB = 0.f;
    int t = blockIdx.x * 256 + tid;
    if (t < TOTAL_B_THREADS) {
        int g = t % NGX;
        int rem = t / NGX;
        int yw = rem % NWIN_Y;
        int i = rem / NWIN_Y;
        int x0 = g * 16;

        int rA = (i * YP + yw) * XD;
        int rB = rA + XD;

        float Fp;
        unsigned cbp;
        if (x0 == 0) {
            Fp = 0.f;
            cbp = 0u;
        } else {
            int c = x0 - 1;
            Fp = g_E[rA + c] + g_E[rB + c];
            cbp = (unsigned)g_ZC[rA + c] | ((unsigned)g_ZC[rB + c] << 1);
        }

#pragma unroll
        for (int half = 0; half < 2; half++) {
            int hb = x0 + half * 8;
            // 8 columns: 2 float4 per row + 8 code bytes per row
            const float4* pA = reinterpret_cast<const float4*>(g_E + rA + hb);
            const float4* pB = reinterpret_cast<const float4*>(g_E + rB + hb);
            float4 a0 = pA[0], a1 = pA[1];
            float4 b0 = pB[0], b1 = pB[1];
            uint2 za = *reinterpret_cast<const uint2*>(g_ZC + rA + hb);
            uint2 zb = *reinterpret_cast<const uint2*>(g_ZC + rB + hb);

#pragma unroll
            for (int j = 0; j < 2; j++) {
                float4 ea = j ? a1 : a0;
                float4 eb = j ? b1 : b0;
                // column codes for 4 columns: zc bytes <= 0x55 -> <<1 stays in-lane
                unsigned cw = (j ? za.y : za.x) | ((j ? zb.y : zb.x) << 1);
                // prevw byte k = code of column k-1 (byte0 = carry)
                unsigned prevw = __byte_perm(cw, cbp, 0x2104);
                // L byte k = lidx of window k ; P byte k = pidx of window k
                unsigned L = ((prevw << 4) & 0xF0F0F0F0u) | (cw & 0x0F0F0F0Fu);
                unsigned P = (prevw & 0xF0F0F0F0u) | ((cw >> 4) & 0x0F0F0F0Fu);

                float F0 = ea.x + eb.x;
                float F1 = ea.y + eb.y;
                float F2 = ea.z + eb.z;
                float F3 = ea.w + eb.w;

                float q0 = Fp + F0;
                float q1 = F0 + F1;
                float q2 = F1 + F2;
                float q3 = F2 + F3;

                float la0 = a_sh[L & 0xFFu];
                float la1 = a_sh[(L >> 8) & 0xFFu];
                float la2 = a_sh[(L >> 16) & 0xFFu];
                float la3 = a_sh[L >> 24];
                float pa0 = a_sh[P & 0xFFu];
                float pa1 = a_sh[(P >> 8) & 0xFFu];
                float pa2 = a_sh[(P >> 16) & 0xFFu];
                float pa3 = a_sh[P >> 24];

                Sq = fmaf(q0, la0, Sq);
                Sq = fmaf(q1, la1, Sq);
                Sq = fmaf(q2, la2, Sq);
                Sq = fmaf(q3, la3, Sq);
                S1 += (la0 + la1) + (la2 + la3);
                S2 += (pa0 + pa1) + (pa2 + pa3);

                // rare path: any window with label byte 0 or 255
                unsigned r = __vcmpeq4(L, 0u) | __vcmpeq4(L, 0xFFFFFFFFu);
                if (r) {
#pragma unroll
                    for (int k = 0; k < 4; k++) {
                        unsigned lb = (L >> (8 * k)) & 0xFFu;
                        if (lb == 0u || lb == 255u)
                            accB += bce8(pred, i, yw, hb + 4 * j + k, lb == 255u);
                    }
                }

                Fp = F3;
                cbp = cw >> 24;
            }
        }

        // group 23: edge window x=384 (right column is zero padding)
        if (g == NGX - 1) {
            float q = Fp;
            unsigned lidx = (cbp << 4) & 0xF0u;
            unsigned pidx = cbp & 0xF0u;
            float la = a_sh[lidx];
            float pa = a_sh[pidx];
            Sq = fmaf(q, la, Sq);
            S1 += la;
            S2 += pa;
            if (lidx == 0u)   // lidx==255 impossible here (low nibble is 0)
                accB += bce8(pred, i, yw, 384, false);
        }
    }
    float accN = fmaf(Sq, -0.125f, S1);   // sum of (1 - q/8)*la
    float accD = S1 + S2;

    // deterministic warp-shuffle reduction
    accN = warp_sum(accN);
    accD = warp_sum(accD);
    accB = warp_sum(accB);
    int lane = tid & 31, warp = tid >> 5;
    if (lane == 0) { wN[warp] = accN; wD[warp] = accD; wB[warp] = accB; }
    __syncthreads();
    if (warp == 0) {
        float vN = lane < 8 ? wN[lane] : 0.f;
        float vD = lane < 8 ? wD[lane] : 0.f;
        float vB = lane < 8 ? wB[lane] : 0.f;
#pragma unroll
        for (int off = 4; off > 0; off >>= 1) {
            vN += __shfl_down_sync(0xffffffffu, vN, off);
            vD += __shfl_down_sync(0xffffffffu, vD, off);
            vB += __shfl_down_sync(0xffffffffu, vB, off);
        }
        if (lane == 0) {
            g_part[3 * blockIdx.x + 0] = vN;
            g_part[3 * blockIdx.x + 1] = vD;
            g_part[3 * blockIdx.x + 2] = vB;
        }
    }

    __threadfence();
    if (tid == 0) {
        unsigned prev = atomicAdd(&g_count, 1u);
        is_last = (prev == B_BLOCKS - 1);
    }
    __syncthreads();
    if (!is_last) return;

    double sN = 0.0, sD = 0.0, sB = 0.0;
    for (int b = tid; b < B_BLOCKS; b += 256) {
        sN += (double)g_part[3 * b + 0];
        sD += (double)g_part[3 * b + 1];
        sB += (double)g_part[3 * b + 2];
    }
    __shared__ double rd[256];
    rd[tid] = sN; __syncthreads();
    for (int s = 128; s > 0; s >>= 1) { if (tid < s) rd[tid] += rd[tid + s]; __syncthreads(); }
    double tN = rd[0]; __syncthreads();
    rd[tid] = sD; __syncthreads();
    for (int s = 128; s > 0; s >>= 1) { if (tid < s) rd[tid] += rd[tid + s]; __syncthreads(); }
    double tD = rd[0]; __syncthreads();
    rd[tid] = sB; __syncthreads();
    for (int s = 128; s > 0; s >>= 1) { if (tid < s) rd[tid] += rd[tid + s]; __syncthreads(); }
    double tB = rd[0];

    if (tid == 0) {
        double dice = 1.0 - (2.0 * tN + 1e-3) / (tD + 1e-3);
        double vol = tB / (8.0 * NP_WIN);
        out[0] = (float)(dice + vol);
    }
}

// ---------------------------------------------------------------------------
extern "C" void kernel_launch(void* const* d_in, const int* in_sizes, int n_in,
                              void* d_out, int out_size) {
    const float* pred   = (const float*)d_in[0];
    const int*   labels = (const int*)d_in[1];
    const float* area   = (const float*)d_in[2];

    k1<<<YD, XD>>>(pred, labels);
    k2<<<B_BLOCKS, 256>>>(pred, area, (float*)d_out);
}